// round 1
// baseline (speedup 1.0000x reference)
#include <cuda_runtime.h>

// Shapes (fixed by the problem)
#define BB 8
#define CC 64
#define HH 32
#define WW 32
#define OO 32
#define QQ 8

// Scratch: sigmoid(x), 8*64*32*32 floats = 2MB (device global, no alloc)
__device__ float g_sig[BB * CC * HH * WW];

__device__ __forceinline__ float sigmoidf(float x) {
    return __fdividef(1.0f, 1.0f + __expf(-x));
}

// 4-input multilinear LUT over 16 corners; input i = bit i (LSB = input 0).
// Lerp-reduction: reduce bit3 (stride 8), bit2 (stride 4), bit1 (stride 2), bit0.
__device__ __forceinline__ float lut4(const float* __restrict__ w,
                                      float x0, float x1, float x2, float x3) {
    float4 a = *(const float4*)(w);
    float4 b = *(const float4*)(w + 4);
    float4 c = *(const float4*)(w + 8);
    float4 d = *(const float4*)(w + 12);
    float v0 = fmaf(x3, c.x - a.x, a.x);
    float v1 = fmaf(x3, c.y - a.y, a.y);
    float v2 = fmaf(x3, c.z - a.z, a.z);
    float v3 = fmaf(x3, c.w - a.w, a.w);
    float v4 = fmaf(x3, d.x - b.x, b.x);
    float v5 = fmaf(x3, d.y - b.y, b.y);
    float v6 = fmaf(x3, d.z - b.z, b.z);
    float v7 = fmaf(x3, d.w - b.w, b.w);
    float u0 = fmaf(x2, v4 - v0, v0);
    float u1 = fmaf(x2, v5 - v1, v1);
    float u2 = fmaf(x2, v6 - v2, v2);
    float u3 = fmaf(x2, v7 - v3, v3);
    float t0 = fmaf(x1, u2 - u0, u0);
    float t1 = fmaf(x1, u3 - u1, u1);
    return fmaf(x0, t1 - t0, t0);
}

__global__ void sigmoid_kernel(const float* __restrict__ x) {
    int i = blockIdx.x * blockDim.x + threadIdx.x;
    const int n4 = BB * CC * HH * WW / 4;
    if (i < n4) {
        float4 v = ((const float4*)x)[i];
        v.x = sigmoidf(v.x);
        v.y = sigmoidf(v.y);
        v.z = sigmoidf(v.z);
        v.w = sigmoidf(v.w);
        ((float4*)g_sig)[i] = v;
    }
}

// Block = (half, b, o): 16 rows x 32 cols of one image, one output head.
// 256 threads, 2 pixels each.
__global__ __launch_bounds__(256) void lut_kernel(
    const float* __restrict__ w0, const float* __restrict__ w1,
    const float* __restrict__ w2, const float* __restrict__ w3,
    const int* __restrict__ ci, float* __restrict__ out)
{
    __shared__ float tile[QQ][18][36];               // 8ch x (16+2 halo rows) x (34 used, 36 stride)
    __shared__ __align__(16) float wsm[416];          // 18*16 + 5*16 + 2*16 + 1*16
    __shared__ int ch[QQ];

    const int half = blockIdx.x;
    const int b = blockIdx.y;
    const int o = blockIdx.z;
    const int tid = threadIdx.x;

    if (tid < QQ) ch[tid] = ci[o * QQ + tid];
    // Weights for this o into smem
    for (int i = tid; i < 288; i += 256) wsm[i] = w0[o * 288 + i];
    if (tid < 80)  wsm[288 + tid] = w1[o * 80 + tid];
    if (tid < 32)  wsm[368 + tid] = w2[o * 32 + tid];
    if (tid < 16)  wsm[400 + tid] = w3[o * 16 + tid];
    __syncthreads();

    const int row0 = half * 16;
    // Fill tile: rows row0-1 .. row0+16, cols -1..32. OOB -> sigmoid(0)=0.5
    for (int idx = tid; idx < QQ * 18 * 34; idx += 256) {
        int q = idx / (18 * 34);
        int rem = idx - q * (18 * 34);
        int r = rem / 34;
        int col = rem - r * 34;
        int gh = row0 - 1 + r;
        int gw = col - 1;
        float v = 0.5f;
        if (gh >= 0 && gh < HH && gw >= 0 && gw < WW)
            v = g_sig[((b * CC + ch[q]) * HH + gh) * WW + gw];
        tile[q][r][col] = v;
    }
    __syncthreads();

    for (int p = tid; p < 16 * 32; p += 256) {
        const int lh = p >> 5;
        const int lw = p & 31;

        // Level 0: 18 LUTs over the 72 patch inputs (t = q*9 + ky*3 + kx)
        float cur[18];
        #pragma unroll
        for (int l = 0; l < 18; l++) {
            float xs[4];
            #pragma unroll
            for (int j = 0; j < 4; j++) {
                const int t = 4 * l + j;
                const int q = t / 9;
                const int k = t - q * 9;
                xs[j] = tile[q][lh + k / 3][lw + k % 3];
            }
            cur[l] = sigmoidf(lut4(&wsm[l * 16], xs[0], xs[1], xs[2], xs[3]));
        }

        // Level 1: 5 LUTs over 18 values + 2x 0.5 pad
        float n1[5];
        #pragma unroll
        for (int l = 0; l < 5; l++) {
            float xs[4];
            #pragma unroll
            for (int j = 0; j < 4; j++) {
                const int t = 4 * l + j;
                xs[j] = (t < 18) ? cur[t] : 0.5f;
            }
            n1[l] = sigmoidf(lut4(&wsm[288 + l * 16], xs[0], xs[1], xs[2], xs[3]));
        }

        // Level 2: 2 LUTs over 5 values + 3x 0.5 pad
        float n2_0 = sigmoidf(lut4(&wsm[368], n1[0], n1[1], n1[2], n1[3]));
        float n2_1 = sigmoidf(lut4(&wsm[384], n1[4], 0.5f, 0.5f, 0.5f));

        // Level 3: final LUT, no sigmoid
        float res = lut4(&wsm[400], n2_0, n2_1, 0.5f, 0.5f);

        const int gh = row0 + lh;
        out[((b * OO + o) * HH + gh) * WW + lw] = res;
    }
}

extern "C" void kernel_launch(void* const* d_in, const int* in_sizes, int n_in,
                              void* d_out, int out_size) {
    const float* x  = (const float*)d_in[0];
    const float* w0 = (const float*)d_in[1];
    const float* w1 = (const float*)d_in[2];
    const float* w2 = (const float*)d_in[3];
    const float* w3 = (const float*)d_in[4];
    const int*   ci = (const int*)d_in[5];
    float* out = (float*)d_out;

    const int n4 = BB * CC * HH * WW / 4;  // 131072
    sigmoid_kernel<<<(n4 + 255) / 256, 256>>>(x);
    lut_kernel<<<dim3(2, BB, OO), 256>>>(w0, w1, w2, w3, ci, out);
}

// round 3
// speedup vs baseline: 2.0202x; 2.0202x over previous
#include <cuda_runtime.h>

// Shapes (fixed by the problem)
#define BB 8
#define CC 64
#define HH 32
#define WW 32
#define OO 32
#define QQ 8

// Scratch: sigmoid(x), 8*64*32*32 floats = 2MB (device global, no alloc)
__device__ float g_sig[BB * CC * HH * WW];

__device__ __forceinline__ float sigmoidf(float x) {
    return __fdividef(1.0f, 1.0f + __expf(-x));
}

// 4-input multilinear LUT over 16 corners; input i = bit i (LSB = input 0).
__device__ __forceinline__ float lut4(const float* __restrict__ w,
                                      float x0, float x1, float x2, float x3) {
    float4 a = *(const float4*)(w);
    float4 b = *(const float4*)(w + 4);
    float4 c = *(const float4*)(w + 8);
    float4 d = *(const float4*)(w + 12);
    float v0 = fmaf(x3, c.x - a.x, a.x);
    float v1 = fmaf(x3, c.y - a.y, a.y);
    float v2 = fmaf(x3, c.z - a.z, a.z);
    float v3 = fmaf(x3, c.w - a.w, a.w);
    float v4 = fmaf(x3, d.x - b.x, b.x);
    float v5 = fmaf(x3, d.y - b.y, b.y);
    float v6 = fmaf(x3, d.z - b.z, b.z);
    float v7 = fmaf(x3, d.w - b.w, b.w);
    float u0 = fmaf(x2, v4 - v0, v0);
    float u1 = fmaf(x2, v5 - v1, v1);
    float u2 = fmaf(x2, v6 - v2, v2);
    float u3 = fmaf(x2, v7 - v3, v3);
    float t0 = fmaf(x1, u2 - u0, u0);
    float t1 = fmaf(x1, u3 - u1, u1);
    return fmaf(x0, t1 - t0, t0);
}

// Bilinear over 4 pre-folded corners (bit0 = x0, bit1 = x1)
__device__ __forceinline__ float lut2(const float* __restrict__ w,
                                      float x0, float x1) {
    float t0 = fmaf(x1, w[2] - w[0], w[0]);
    float t1 = fmaf(x1, w[3] - w[1], w[1]);
    return fmaf(x0, t1 - t0, t0);
}

__global__ void sigmoid_kernel(const float* __restrict__ x) {
    int i = blockIdx.x * blockDim.x + threadIdx.x;
    const int n4 = BB * CC * HH * WW / 4;
    if (i < n4) {
        float4 v = ((const float4*)x)[i];
        v.x = sigmoidf(v.x);
        v.y = sigmoidf(v.y);
        v.z = sigmoidf(v.z);
        v.w = sigmoidf(v.w);
        ((float4*)g_sig)[i] = v;
    }
}

// Block = (quarter, b, o): 8 rows x 32 cols of one image, one output head.
// 256 threads, 1 pixel each. 2 CTAs/SM target.
//
// wsm layout:
//   [0..287]    w0 (18 tables x 16)
//   [288..351]  w1 tables 0..3 (full 16-corner)
//   [352..367]  w1 table 4 raw (only used as fold source)
//   [368..383]  w2 table 0 (full)
//   [384..399]  w2 table 1 raw (fold source)
//   [400..415]  w3 raw (fold source)
//   [416..419]  FOLDED w1 table 4  (bilinear: corners over bits 0,1)
//   [420..423]  FOLDED w3          (bilinear)
//   [424..425]  FOLDED w2 table 1  (linear: corners over bit 0)
__global__ __launch_bounds__(256, 2) void lut_kernel(
    const float* __restrict__ w0, const float* __restrict__ w1,
    const float* __restrict__ w2, const float* __restrict__ w3,
    const int* __restrict__ ci, float* __restrict__ out)
{
    __shared__ float tile[QQ][10][36];                // 8ch x (8+2 halo) x (34 used, 36 stride)
    __shared__ __align__(16) float wsm[432];
    __shared__ int ch[QQ];

    const int quarter = blockIdx.x;
    const int b = blockIdx.y;
    const int o = blockIdx.z;
    const int tid = threadIdx.x;

    if (tid < QQ) ch[tid] = ci[o * QQ + tid];
    for (int i = tid; i < 288; i += 256) wsm[i] = w0[o * 288 + i];
    if (tid < 80)  wsm[288 + tid] = w1[o * 80 + tid];
    if (tid < 32)  wsm[368 + tid] = w2[o * 32 + tid];
    if (tid < 16)  wsm[400 + tid] = w3[o * 16 + tid];
    __syncthreads();

    // Fold constant-0.5 inputs into NEW slots (no aliasing with sources).
    if (tid < 4) {
        // w1 table 4: inputs 2,3 pinned at 0.5 -> average over bits 2,3
        wsm[416 + tid] = 0.25f * (wsm[352 + tid] + wsm[356 + tid] +
                                  wsm[360 + tid] + wsm[364 + tid]);
    } else if (tid < 8) {
        // w3: inputs 2,3 pinned at 0.5
        int i = tid - 4;
        wsm[420 + i] = 0.25f * (wsm[400 + i] + wsm[404 + i] +
                                wsm[408 + i] + wsm[412 + i]);
    } else if (tid < 10) {
        // w2 table 1: inputs 1,2,3 pinned at 0.5 -> average over bits 1,2,3
        int i = tid - 8;
        wsm[424 + i] = 0.125f * (wsm[384 + i] + wsm[386 + i] + wsm[388 + i] + wsm[390 + i] +
                                 wsm[392 + i] + wsm[394 + i] + wsm[396 + i] + wsm[398 + i]);
    }

    const int row0 = quarter * 8;
    // Fill tile: rows row0-1 .. row0+8, cols -1..32. OOB -> sigmoid(0)=0.5
    for (int idx = tid; idx < QQ * 10 * 34; idx += 256) {
        int q = idx / (10 * 34);
        int rem = idx - q * (10 * 34);
        int r = rem / 34;
        int col = rem - r * 34;
        int gh = row0 - 1 + r;
        int gw = col - 1;
        float v = 0.5f;
        if (gh >= 0 && gh < HH && gw >= 0 && gw < WW)
            v = g_sig[((b * CC + ch[q]) * HH + gh) * WW + gw];
        tile[q][r][col] = v;
    }
    __syncthreads();

    const int lh = tid >> 5;          // 0..7
    const int lw = tid & 31;          // 0..31

    // Level 0: 18 LUTs over the 72 patch inputs (t = q*9 + ky*3 + kx)
    float cur[18];
    #pragma unroll
    for (int l = 0; l < 18; l++) {
        float xs[4];
        #pragma unroll
        for (int j = 0; j < 4; j++) {
            const int t = 4 * l + j;
            const int q = t / 9;
            const int k = t - q * 9;
            xs[j] = tile[q][lh + k / 3][lw + k % 3];
        }
        cur[l] = sigmoidf(lut4(&wsm[l * 16], xs[0], xs[1], xs[2], xs[3]));
    }

    // Level 1: 4 full LUTs + 1 folded bilinear (inputs 18,19 were 0.5-pad)
    float n1[5];
    #pragma unroll
    for (int l = 0; l < 4; l++) {
        n1[l] = sigmoidf(lut4(&wsm[288 + l * 16],
                              cur[4 * l], cur[4 * l + 1], cur[4 * l + 2], cur[4 * l + 3]));
    }
    n1[4] = sigmoidf(lut2(&wsm[416], cur[16], cur[17]));

    // Level 2: 1 full LUT + 1 folded linear
    float n2_0 = sigmoidf(lut4(&wsm[368], n1[0], n1[1], n1[2], n1[3]));
    float n2_1 = sigmoidf(fmaf(n1[4], wsm[425] - wsm[424], wsm[424]));

    // Level 3: folded bilinear, no sigmoid
    float res = lut2(&wsm[420], n2_0, n2_1);

    out[((b * OO + o) * HH + row0 + lh) * WW + lw] = res;
}

extern "C" void kernel_launch(void* const* d_in, const int* in_sizes, int n_in,
                              void* d_out, int out_size) {
    const float* x  = (const float*)d_in[0];
    const float* w0 = (const float*)d_in[1];
    const float* w1 = (const float*)d_in[2];
    const float* w2 = (const float*)d_in[3];
    const float* w3 = (const float*)d_in[4];
    const int*   ci = (const int*)d_in[5];
    float* out = (float*)d_out;

    const int n4 = BB * CC * HH * WW / 4;  // 131072
    sigmoid_kernel<<<(n4 + 255) / 256, 256>>>(x);
    lut_kernel<<<dim3(4, BB, OO), 256>>>(w0, w1, w2, w3, ci, out);
}